// round 2
// baseline (speedup 1.0000x reference)
#include <cuda_runtime.h>
#include <cstdint>

#define FLOOR_V 1e-6f
#define MELS 128
#define FRAMES 1024
#define U 4  // rows per warp-iteration

// One warp per (batch,time) row of 128 mel bins; 4 rows in flight per warp.
// Closed-form separable replacement for the width-axis conv:
//   smoothed[w] = alpha^(511-w) * R / S,  R = sum_m x[m] * alpha^m
// Hot path: per-lane bound part <= FLOOR/(32*cb) + one vote proves every
// smoothed value clamps to FLOOR, so smoothed^-alpha == KA (warp-uniform),
// with no cross-lane reduction at all.
__global__ __launch_bounds__(256, 8)
void pcen_kernel(const float* __restrict__ in,
                 const float* __restrict__ p_alpha,
                 const float* __restrict__ p_delta,
                 const float* __restrict__ p_root,
                 float* __restrict__ out,
                 int num_rows) {
    const float alpha = __ldg(p_alpha);
    const float delta = __ldg(p_delta);
    const float root  = __ldg(p_root);

    const int lane = threadIdx.x & 31;
    const int warp_global = (blockIdx.x * blockDim.x + threadIdx.x) >> 5;
    const int nwarps = (gridDim.x * blockDim.x) >> 5;

    // ---- warp-invariant derived constants ----
    const float la = __log2f(alpha);
    float S;
    {
        const float one_minus_a = 1.0f - alpha;
        if (fabsf(one_minus_a) > 1e-12f)
            S = (1.0f - exp2f((float)FRAMES * la)) / one_minus_a;
        else
            S = (float)FRAMES;
    }
    const float KA    = __powf(FLOOR_V, -alpha);   // FLOOR^-alpha
    const float droot = __powf(delta, root);       // delta^root
    const float inv_S = 1.0f / S;
    const float ralpha = 1.0f / alpha;

    // Per-lane dot weights alpha^m for m = 4*lane + i
    const float w0 = exp2f((float)(4 * lane) * la);
    const float w1 = w0 * alpha;
    const float w2 = w1 * alpha;
    const float w3 = w2 * alpha;

    // Per-lane conv coefficients c_w = alpha^(511-w)/S for the general path
    const float c0 = exp2f((float)((FRAMES / 2 - 1) - 4 * lane) * la) * inv_S;
    const float c1 = c0 * ralpha;
    const float c2 = c1 * ralpha;
    const float c3 = c2 * ralpha;

    // Upper bound over all w of c_w; per-lane partial threshold:
    // R <= 32*max_lane(part), so part <= FLOOR/(32*cb)  =>  all smoothed clamp.
    const float cb = fmaxf(exp2f((float)(FRAMES / 2 - 1) * la),
                           exp2f((float)(FRAMES / 2 - MELS) * la)) * inv_S;
    const float thresh = FLOOR_V / (32.0f * cb);

    const float4* __restrict__ in4  = reinterpret_cast<const float4*>(in);
    float4* __restrict__       out4 = reinterpret_cast<float4*>(out);

    const int nquads = num_rows >> 2;  // num_rows = 65536, divisible by 4

    for (int q = warp_global; q < nquads; q += nwarps) {
        const int base = (q << 2) * (MELS / 4) + lane;

        // Front-batched independent loads: 4 rows in flight (MLP=4)
        float4 v[U];
#pragma unroll
        for (int k = 0; k < U; k++) v[k] = in4[base + k * (MELS / 4)];

        float x[U][4], part[U];
#pragma unroll
        for (int k = 0; k < U; k++) {
            x[k][0] = fmaxf(v[k].x, FLOOR_V);
            x[k][1] = fmaxf(v[k].y, FLOOR_V);
            x[k][2] = fmaxf(v[k].z, FLOOR_V);
            x[k][3] = fmaxf(v[k].w, FLOOR_V);
            float p = x[k][0] * w0;
            p = fmaf(x[k][1], w1, p);
            p = fmaf(x[k][2], w2, p);
            p = fmaf(x[k][3], w3, p);
            part[k] = p;
        }

        const bool ok = (part[0] <= thresh) & (part[1] <= thresh) &
                        (part[2] <= thresh) & (part[3] <= thresh);

        float pm[U][4];
        if (__all_sync(0xffffffffu, ok)) {
            // Hot path: every smoothed value clamps to FLOOR
#pragma unroll
            for (int k = 0; k < U; k++) {
                pm[k][0] = KA; pm[k][1] = KA; pm[k][2] = KA; pm[k][3] = KA;
            }
        } else {
            // General path: exact row sums + per-bin smoothed (not taken here)
#pragma unroll
            for (int k = 0; k < U; k++) {
                float r = part[k];
                r += __shfl_xor_sync(0xffffffffu, r, 16);
                r += __shfl_xor_sync(0xffffffffu, r, 8);
                r += __shfl_xor_sync(0xffffffffu, r, 4);
                r += __shfl_xor_sync(0xffffffffu, r, 2);
                r += __shfl_xor_sync(0xffffffffu, r, 1);
                pm[k][0] = __powf(fmaxf(c0 * r, FLOOR_V), -alpha);
                pm[k][1] = __powf(fmaxf(c1 * r, FLOOR_V), -alpha);
                pm[k][2] = __powf(fmaxf(c2 * r, FLOOR_V), -alpha);
                pm[k][3] = __powf(fmaxf(c3 * r, FLOOR_V), -alpha);
            }
        }

#pragma unroll
        for (int k = 0; k < U; k++) {
            float4 o;
            o.x = __powf(fmaf(x[k][0], pm[k][0], delta), root) - droot;
            o.y = __powf(fmaf(x[k][1], pm[k][1], delta), root) - droot;
            o.z = __powf(fmaf(x[k][2], pm[k][2], delta), root) - droot;
            o.w = __powf(fmaf(x[k][3], pm[k][3], delta), root) - droot;
            out4[base + k * (MELS / 4)] = o;
        }
    }

    // Tail (num_rows not divisible by 4): single-row path
    for (int row = (nquads << 2) + warp_global; row < num_rows; row += nwarps) {
        const int idx = row * (MELS / 4) + lane;
        const float4 v = in4[idx];
        float x0 = fmaxf(v.x, FLOOR_V), x1 = fmaxf(v.y, FLOOR_V);
        float x2 = fmaxf(v.z, FLOOR_V), x3 = fmaxf(v.w, FLOOR_V);
        float p = x0 * w0;
        p = fmaf(x1, w1, p); p = fmaf(x2, w2, p); p = fmaf(x3, w3, p);
        float pm0, pm1, pm2, pm3;
        if (__all_sync(0xffffffffu, p <= thresh)) {
            pm0 = pm1 = pm2 = pm3 = KA;
        } else {
            float r = p;
            r += __shfl_xor_sync(0xffffffffu, r, 16);
            r += __shfl_xor_sync(0xffffffffu, r, 8);
            r += __shfl_xor_sync(0xffffffffu, r, 4);
            r += __shfl_xor_sync(0xffffffffu, r, 2);
            r += __shfl_xor_sync(0xffffffffu, r, 1);
            pm0 = __powf(fmaxf(c0 * r, FLOOR_V), -alpha);
            pm1 = __powf(fmaxf(c1 * r, FLOOR_V), -alpha);
            pm2 = __powf(fmaxf(c2 * r, FLOOR_V), -alpha);
            pm3 = __powf(fmaxf(c3 * r, FLOOR_V), -alpha);
        }
        float4 o;
        o.x = __powf(fmaf(x0, pm0, delta), root) - droot;
        o.y = __powf(fmaf(x1, pm1, delta), root) - droot;
        o.z = __powf(fmaf(x2, pm2, delta), root) - droot;
        o.w = __powf(fmaf(x3, pm3, delta), root) - droot;
        out4[idx] = o;
    }
}

extern "C" void kernel_launch(void* const* d_in, const int* in_sizes, int n_in,
                              void* d_out, int out_size) {
    const float* inputs = (const float*)d_in[0];
    const float* alpha  = (const float*)d_in[1];
    const float* delta  = (const float*)d_in[2];
    const float* root   = (const float*)d_in[3];
    float* out = (float*)d_out;

    const int num_rows = in_sizes[0] / MELS;  // 64 * 1024 = 65536

    const int threads = 256;
    const int blocks = 1184;  // 148 SMs * 8 blocks
    pcen_kernel<<<blocks, threads>>>(inputs, alpha, delta, root, out, num_rows);
}

// round 3
// speedup vs baseline: 1.5000x; 1.5000x over previous
#include <cuda_runtime.h>
#include <cstdint>

#define FLOOR_V 1e-6f
#define MELS 128
#define FRAMES 1024
#define U 2  // rows per warp-iteration (kept small: no spills)

// One warp per (batch,time) row of 128 mel bins; 2 rows in flight per warp.
// Closed-form separable replacement for the width-axis conv:
//   smoothed[w] = alpha^(511-w) * R / S,  R = sum_m x[m] * alpha^m
// Hot path: per-lane bound part <= FLOOR/(32*cb) + one warp vote proves every
// smoothed value clamps to FLOOR, so smoothed^-alpha == KA (warp-uniform),
// with no cross-lane reduction at all.
// NOTE: no min-blocks clause in launch bounds — R2 showed capping to 32 regs
// forces local-memory spills (L1 50%) and regresses 36%.
__global__ __launch_bounds__(256)
void pcen_kernel(const float* __restrict__ in,
                 const float* __restrict__ p_alpha,
                 const float* __restrict__ p_delta,
                 const float* __restrict__ p_root,
                 float* __restrict__ out,
                 int num_rows) {
    const float alpha = __ldg(p_alpha);
    const float delta = __ldg(p_delta);
    const float root  = __ldg(p_root);

    const int lane = threadIdx.x & 31;
    const int warp_global = (blockIdx.x * blockDim.x + threadIdx.x) >> 5;
    const int nwarps = (gridDim.x * blockDim.x) >> 5;

    // ---- warp-invariant derived constants ----
    const float la = __log2f(alpha);
    float S;
    {
        const float one_minus_a = 1.0f - alpha;
        if (fabsf(one_minus_a) > 1e-12f)
            S = (1.0f - exp2f((float)FRAMES * la)) / one_minus_a;
        else
            S = (float)FRAMES;
    }
    const float KA    = __powf(FLOOR_V, -alpha);   // FLOOR^-alpha
    const float droot = __powf(delta, root);       // delta^root
    const float inv_S = 1.0f / S;
    const float ralpha = 1.0f / alpha;

    // Per-lane dot weights alpha^m for m = 4*lane + i
    const float w0 = exp2f((float)(4 * lane) * la);
    const float w1 = w0 * alpha;
    const float w2 = w1 * alpha;
    const float w3 = w2 * alpha;

    // Per-lane conv coefficients c_w = alpha^(511-w)/S (general path only)
    const float c0 = exp2f((float)((FRAMES / 2 - 1) - 4 * lane) * la) * inv_S;
    const float c1 = c0 * ralpha;
    const float c2 = c1 * ralpha;
    const float c3 = c2 * ralpha;

    // Upper bound over all w of c_w; per-lane partial threshold:
    // R <= 32*max_lane(part), so part <= FLOOR/(32*cb)  =>  all smoothed clamp.
    const float cb = fmaxf(exp2f((float)(FRAMES / 2 - 1) * la),
                           exp2f((float)(FRAMES / 2 - MELS) * la)) * inv_S;
    const float thresh = FLOOR_V / (32.0f * cb);

    const float4* __restrict__ in4  = reinterpret_cast<const float4*>(in);
    float4* __restrict__       out4 = reinterpret_cast<float4*>(out);

    const int npairs = num_rows >> 1;  // 65536 rows -> 32768 pairs

    for (int q = warp_global; q < npairs; q += nwarps) {
        const int base = (q << 1) * (MELS / 4) + lane;

        // Front-batched independent loads: 2 rows in flight
        float4 v0 = in4[base];
        float4 v1 = in4[base + (MELS / 4)];

        float x00 = fmaxf(v0.x, FLOOR_V), x01 = fmaxf(v0.y, FLOOR_V);
        float x02 = fmaxf(v0.z, FLOOR_V), x03 = fmaxf(v0.w, FLOOR_V);
        float x10 = fmaxf(v1.x, FLOOR_V), x11 = fmaxf(v1.y, FLOOR_V);
        float x12 = fmaxf(v1.z, FLOOR_V), x13 = fmaxf(v1.w, FLOOR_V);

        float p0 = x00 * w0;
        p0 = fmaf(x01, w1, p0); p0 = fmaf(x02, w2, p0); p0 = fmaf(x03, w3, p0);
        float p1 = x10 * w0;
        p1 = fmaf(x11, w1, p1); p1 = fmaf(x12, w2, p1); p1 = fmaf(x13, w3, p1);

        float pm00, pm01, pm02, pm03, pm10, pm11, pm12, pm13;
        if (__all_sync(0xffffffffu, (p0 <= thresh) & (p1 <= thresh))) {
            // Hot path: every smoothed value clamps to FLOOR
            pm00 = pm01 = pm02 = pm03 = KA;
            pm10 = pm11 = pm12 = pm13 = KA;
        } else {
            // General path: exact row sums + per-bin smoothed (not taken here)
            float r0 = p0, r1 = p1;
#pragma unroll
            for (int s = 16; s >= 1; s >>= 1) {
                r0 += __shfl_xor_sync(0xffffffffu, r0, s);
                r1 += __shfl_xor_sync(0xffffffffu, r1, s);
            }
            pm00 = __powf(fmaxf(c0 * r0, FLOOR_V), -alpha);
            pm01 = __powf(fmaxf(c1 * r0, FLOOR_V), -alpha);
            pm02 = __powf(fmaxf(c2 * r0, FLOOR_V), -alpha);
            pm03 = __powf(fmaxf(c3 * r0, FLOOR_V), -alpha);
            pm10 = __powf(fmaxf(c0 * r1, FLOOR_V), -alpha);
            pm11 = __powf(fmaxf(c1 * r1, FLOOR_V), -alpha);
            pm12 = __powf(fmaxf(c2 * r1, FLOOR_V), -alpha);
            pm13 = __powf(fmaxf(c3 * r1, FLOOR_V), -alpha);
        }

        float4 o0, o1;
        o0.x = __powf(fmaf(x00, pm00, delta), root) - droot;
        o0.y = __powf(fmaf(x01, pm01, delta), root) - droot;
        o0.z = __powf(fmaf(x02, pm02, delta), root) - droot;
        o0.w = __powf(fmaf(x03, pm03, delta), root) - droot;
        o1.x = __powf(fmaf(x10, pm10, delta), root) - droot;
        o1.y = __powf(fmaf(x11, pm11, delta), root) - droot;
        o1.z = __powf(fmaf(x12, pm12, delta), root) - droot;
        o1.w = __powf(fmaf(x13, pm13, delta), root) - droot;

        out4[base] = o0;
        out4[base + (MELS / 4)] = o1;
    }

    // Tail (odd num_rows): single-row path
    for (int row = (npairs << 1) + warp_global; row < num_rows; row += nwarps) {
        const int idx = row * (MELS / 4) + lane;
        const float4 v = in4[idx];
        float x0 = fmaxf(v.x, FLOOR_V), x1 = fmaxf(v.y, FLOOR_V);
        float x2 = fmaxf(v.z, FLOOR_V), x3 = fmaxf(v.w, FLOOR_V);
        float p = x0 * w0;
        p = fmaf(x1, w1, p); p = fmaf(x2, w2, p); p = fmaf(x3, w3, p);
        float pm0, pm1, pm2, pm3;
        if (__all_sync(0xffffffffu, p <= thresh)) {
            pm0 = pm1 = pm2 = pm3 = KA;
        } else {
            float r = p;
#pragma unroll
            for (int s = 16; s >= 1; s >>= 1)
                r += __shfl_xor_sync(0xffffffffu, r, s);
            pm0 = __powf(fmaxf(c0 * r, FLOOR_V), -alpha);
            pm1 = __powf(fmaxf(c1 * r, FLOOR_V), -alpha);
            pm2 = __powf(fmaxf(c2 * r, FLOOR_V), -alpha);
            pm3 = __powf(fmaxf(c3 * r, FLOOR_V), -alpha);
        }
        float4 o;
        o.x = __powf(fmaf(x0, pm0, delta), root) - droot;
        o.y = __powf(fmaf(x1, pm1, delta), root) - droot;
        o.z = __powf(fmaf(x2, pm2, delta), root) - droot;
        o.w = __powf(fmaf(x3, pm3, delta), root) - droot;
        out4[idx] = o;
    }
}

extern "C" void kernel_launch(void* const* d_in, const int* in_sizes, int n_in,
                              void* d_out, int out_size) {
    const float* inputs = (const float*)d_in[0];
    const float* alpha  = (const float*)d_in[1];
    const float* delta  = (const float*)d_in[2];
    const float* root   = (const float*)d_in[3];
    float* out = (float*)d_out;

    const int num_rows = in_sizes[0] / MELS;  // 64 * 1024 = 65536

    const int threads = 256;
    const int blocks = 1184;  // 148 SMs * 8 blocks, grid-stride
    pcen_kernel<<<blocks, threads>>>(inputs, alpha, delta, root, out, num_rows);
}